// round 3
// baseline (speedup 1.0000x reference)
#include <cuda_runtime.h>
#include <cuda_fp16.h>
#include <cstdint>
#include <cfloat>

// ---------------- problem constants ----------------
constexpr int  kWindow = 512, kE = 8, kC = 128;
constexpr long kLseq   = 2000000;
constexpr int  kNwin   = 3906;                 // L / WINDOW
constexpr int  kMrows  = 8 * kNwin;            // 31248
constexpr int  kMtile  = 64;
constexpr int  kMblocks = (kMrows + kMtile - 1) / kMtile;  // 489
constexpr int  kK      = 4096;                 // WINDOW * E
constexpr int  kKc     = 64;                   // K per stage
constexpr int  kKIter  = kK / kKc;             // 64
constexpr int  kN      = 256;                  // conv1: n 0..127, conv2: n 128..255

// smem: A32 staging 3x16KB | B16 3x32KB | A16 3x8KB
constexpr int  OFF_B16 = 49152;
constexpr int  OFF_A16 = 49152 + 3 * 32768;    // 147456
constexpr unsigned kDynSmem = 147456 + 3 * 8192;  // 172032

// ---------------- device scratch ----------------
static __device__ __align__(16) __half g_wh[(size_t)kN * kK];   // 2 MB
static __device__ float g_gmax[8 * kC];

// ---------------- helpers ----------------
__device__ __forceinline__ uint32_t smem_u32(const void* p) {
    return (uint32_t)__cvta_generic_to_shared(p);
}
#define SW128(off) ((uint32_t)(off) ^ ((((uint32_t)(off)) >> 3) & 0x70u))

__device__ __forceinline__ void cpa16(uint32_t dst, const void* src) {
    asm volatile("cp.async.cg.shared.global [%0], [%1], 16;"
        :: "r"(dst), "l"(__cvta_generic_to_global(src)) : "memory");
}
__device__ __forceinline__ void cpa_commit() { asm volatile("cp.async.commit_group;" ::: "memory"); }
__device__ __forceinline__ void cpa_wait1()  { asm volatile("cp.async.wait_group 1;" ::: "memory"); }

__device__ __forceinline__ void ldsm4(uint32_t& r0, uint32_t& r1, uint32_t& r2, uint32_t& r3,
                                      uint32_t addr) {
    asm volatile("ldmatrix.sync.aligned.m8n8.x4.shared.b16 {%0,%1,%2,%3}, [%4];"
        : "=r"(r0), "=r"(r1), "=r"(r2), "=r"(r3) : "r"(addr));
}
__device__ __forceinline__ void mma16816(float* c, const uint32_t* a, const uint32_t* b) {
    asm volatile("mma.sync.aligned.m16n8k16.row.col.f32.f16.f16.f32 "
        "{%0,%1,%2,%3}, {%4,%5,%6,%7}, {%8,%9}, {%0,%1,%2,%3};"
        : "+f"(c[0]), "+f"(c[1]), "+f"(c[2]), "+f"(c[3])
        : "r"(a[0]), "r"(a[1]), "r"(a[2]), "r"(a[3]), "r"(b[0]), "r"(b[1]));
}
__device__ __forceinline__ void atomMaxF(float* a, float v) {
    if (v >= 0.f) atomicMax((int*)a, __float_as_int(v));
    else          atomicMin((unsigned int*)a, __float_as_uint(v));
}

// ---------------- pack weights: W[n][k], n=0..127 conv1, 128..255 conv2; k = w*8+e
__global__ void k_pack(const float* __restrict__ w1, const float* __restrict__ w2) {
    int t = blockIdx.x * blockDim.x + threadIdx.x;   // 0 .. 1048575
    int n = t >> 12, k = t & 4095;
    int c = n & 127, s = n >> 7;
    int e = k & 7, w = k >> 3;
    float v = (s ? w2 : w1)[(c * kE + e) * kWindow + w];
    g_wh[(size_t)n * kK + k] = __float2half_rn(v);
}

__global__ void k_init() { g_gmax[threadIdx.x] = -FLT_MAX; }

// ---------------- main fused GEMM ----------------
__global__ void __launch_bounds__(256, 1)
k_gemm(const float* __restrict__ x, const float* __restrict__ cb1, const float* __restrict__ cb2) {
    extern __shared__ char dsm[];
    __shared__ float sb1[128], sb2[128];

    const int tid = threadIdx.x, lane = tid & 31, wid = tid >> 5;
    const int wn = wid & 3, wm = wid >> 2;          // warp grid 2(M) x 4(N)
    const int qn = lane & 3, qm = lane >> 2;

    if (tid < 128) { sb1[tid] = cb1[tid]; sb2[tid] = cb2[tid]; }

    const long m0 = (long)blockIdx.x * kMtile;

    // A-load row pointers: thread covers rows q*16 + (tid>>4), q=0..3
    const float* rowp[4];
    #pragma unroll
    for (int q = 0; q < 4; q++) {
        long gm = m0 + q * 16 + (tid >> 4);
        if (gm >= kMrows) gm = 0;                   // clamp; excluded in epilogue
        int b = (int)(gm / kNwin);
        int n = (int)(gm - (long)b * kNwin);
        rowp[q] = x + (size_t)b * ((size_t)kLseq * kE) + (size_t)n * kK;
    }
    const int gcolA = (tid & 15) * 4;               // float offset in 64-float slice

    auto issue = [&](int kc) {
        const int s = kc % 3;
        const uint32_t a32 = smem_u32(dsm) + s * 16384;
        const uint32_t b16 = smem_u32(dsm) + OFF_B16 + s * 32768;
        #pragma unroll
        for (int q = 0; q < 4; q++)                 // A: 1024 granules
            cpa16(a32 + (uint32_t)(q * 256 + tid) * 16, rowp[q] + kc * kKc + gcolA);
        #pragma unroll
        for (int q = 0; q < 8; q++) {               // B: 2048 granules
            int g = q * 256 + tid;
            cpa16(b16 + SW128(g * 16),
                  g_wh + (size_t)(g >> 3) * kK + kc * kKc + (g & 7) * 8);
        }
    };

    issue(0); cpa_commit();
    issue(1); cpa_commit();

    float acc[2][8][4];
    #pragma unroll
    for (int t = 0; t < 2; t++)
        #pragma unroll
        for (int j = 0; j < 8; j++)
            #pragma unroll
            for (int e = 0; e < 4; e++) acc[t][j][e] = 0.f;

    // per-lane ldmatrix geometry
    const int gA = lane >> 3;
    const int rowAo = ((gA & 1) ? 8 : 0) + (lane & 7);
    const int colA  = (gA >> 1) ? 16 : 0;
    const int rowBo = ((gA >> 1) ? 8 : 0) + (lane & 7);
    const int colB  = (gA & 1) ? 16 : 0;

    #pragma unroll 1
    for (int kc = 0; kc < kKIter; kc++) {
        const int s = kc % 3;
        char* a32p = dsm + s * 16384;
        char* a16p = dsm + OFF_A16 + s * 8192;

        cpa_wait1();
        __syncthreads();

        // convert fp32 staging -> fp16 A tile (row = tid>>2, quarter = tid&3)
        {
            const int r = tid >> 2, qq = tid & 3;
            const float4* src = (const float4*)(a32p + r * 256 + qq * 64);
            float4 f0 = src[0], f1 = src[1], f2 = src[2], f3 = src[3];
            uint32_t h[8];
            __half2 t0 = __floats2half2_rn(f0.x, f0.y), t1 = __floats2half2_rn(f0.z, f0.w);
            __half2 t2 = __floats2half2_rn(f1.x, f1.y), t3 = __floats2half2_rn(f1.z, f1.w);
            __half2 t4 = __floats2half2_rn(f2.x, f2.y), t5 = __floats2half2_rn(f2.z, f2.w);
            __half2 t6 = __floats2half2_rn(f3.x, f3.y), t7 = __floats2half2_rn(f3.z, f3.w);
            h[0] = *(uint32_t*)&t0; h[1] = *(uint32_t*)&t1; h[2] = *(uint32_t*)&t2; h[3] = *(uint32_t*)&t3;
            h[4] = *(uint32_t*)&t4; h[5] = *(uint32_t*)&t5; h[6] = *(uint32_t*)&t6; h[7] = *(uint32_t*)&t7;
            uint32_t base = (uint32_t)(r * 128 + qq * 32);
            *(uint4*)(a16p + SW128(base))      = make_uint4(h[0], h[1], h[2], h[3]);
            *(uint4*)(a16p + SW128(base + 16)) = make_uint4(h[4], h[5], h[6], h[7]);
        }
        __syncthreads();

        if (kc + 2 < kKIter) issue(kc + 2);
        cpa_commit();

        // compute this stage: 4 k16 steps
        const uint32_t a16 = smem_u32(dsm) + OFF_A16 + s * 8192;
        const uint32_t b16 = smem_u32(dsm) + OFF_B16 + s * 32768;
        #pragma unroll
        for (int kk = 0; kk < 4; kk++) {
            uint32_t a[2][4];
            #pragma unroll
            for (int t = 0; t < 2; t++) {
                int row = wm * 32 + t * 16 + rowAo;
                uint32_t addr = a16 + row * 128 + (((uint32_t)(kk * 32 + colA)) ^ ((row & 7) << 4));
                ldsm4(a[t][0], a[t][1], a[t][2], a[t][3], addr);
            }
            uint32_t bf[8][2];
            #pragma unroll
            for (int j2 = 0; j2 < 4; j2++) {
                int row = wn * 64 + j2 * 16 + rowBo;
                uint32_t addr = b16 + row * 128 + (((uint32_t)(kk * 32 + colB)) ^ ((row & 7) << 4));
                uint32_t r0, r1, r2, r3;
                ldsm4(r0, r1, r2, r3, addr);
                bf[2 * j2][0] = r0; bf[2 * j2][1] = r1;
                bf[2 * j2 + 1][0] = r2; bf[2 * j2 + 1][1] = r3;
            }
            #pragma unroll
            for (int t = 0; t < 2; t++)
                #pragma unroll
                for (int j = 0; j < 8; j++)
                    mma16816(acc[t][j], a[t], bf[j]);
        }
    }

    // ---------------- fused epilogue ----------------
    __syncthreads();                                  // all compute done before reuse of dsm
    float* gate = (float*)dsm;                        // [64][128] fp32 = 32 KB

    if (wn >= 2) {                                    // conv2: sigmoid gates
        #pragma unroll
        for (int t = 0; t < 2; t++)
            #pragma unroll
            for (int j = 0; j < 8; j++) {
                int cb = (wn - 2) * 64 + j * 8 + qn * 2;
                float b2e = sb2[cb], b2o = sb2[cb + 1];
                #pragma unroll
                for (int rb = 0; rb < 2; rb++) {
                    int row = wm * 32 + t * 16 + qm + rb * 8;
                    float ge = acc[t][j][rb * 2 + 0] + b2e;
                    float go = acc[t][j][rb * 2 + 1] + b2o;
                    gate[row * 128 + cb]     = 1.f / (1.f + __expf(-ge));
                    gate[row * 128 + cb + 1] = 1.f / (1.f + __expf(-go));
                }
            }
    }
    __syncthreads();

    if (wn < 2) {                                     // conv1: value * gate, max-pool
        long mlast = m0 + 63;
        const bool uniform = (mlast < kMrows) && ((m0 / kNwin) == (mlast / kNwin));
        const int bb0 = (int)(m0 / kNwin);

        #pragma unroll
        for (int j = 0; j < 8; j++) {
            int cb = wn * 64 + j * 8 + qn * 2;
            float b1e = sb1[cb], b1o = sb1[cb + 1];
            if (uniform) {
                float vE = -FLT_MAX, vO = -FLT_MAX;
                #pragma unroll
                for (int t = 0; t < 2; t++)
                    #pragma unroll
                    for (int rb = 0; rb < 2; rb++) {
                        int row = wm * 32 + t * 16 + qm + rb * 8;
                        vE = fmaxf(vE, (acc[t][j][rb * 2 + 0] + b1e) * gate[row * 128 + cb]);
                        vO = fmaxf(vO, (acc[t][j][rb * 2 + 1] + b1o) * gate[row * 128 + cb + 1]);
                    }
                #pragma unroll
                for (int o = 4; o < 32; o <<= 1) {
                    vE = fmaxf(vE, __shfl_xor_sync(0xFFFFFFFFu, vE, o));
                    vO = fmaxf(vO, __shfl_xor_sync(0xFFFFFFFFu, vO, o));
                }
                if (qm == 0) {
                    atomMaxF(&g_gmax[bb0 * kC + cb],     vE);
                    atomMaxF(&g_gmax[bb0 * kC + cb + 1], vO);
                }
            } else {
                #pragma unroll
                for (int t = 0; t < 2; t++)
                    #pragma unroll
                    for (int rb = 0; rb < 2; rb++) {
                        long gm = m0 + wm * 32 + t * 16 + qm + rb * 8;
                        if (gm < kMrows) {
                            int row = wm * 32 + t * 16 + qm + rb * 8;
                            int bb = (int)(gm / kNwin);
                            atomMaxF(&g_gmax[bb * kC + cb],
                                     (acc[t][j][rb * 2 + 0] + b1e) * gate[row * 128 + cb]);
                            atomMaxF(&g_gmax[bb * kC + cb + 1],
                                     (acc[t][j][rb * 2 + 1] + b1o) * gate[row * 128 + cb + 1]);
                        }
                    }
            }
        }
    }
}

// ---------------- FC head ----------------
__global__ void k_fc(const float* __restrict__ f1w, const float* __restrict__ f1b,
                     const float* __restrict__ f2w, const float* __restrict__ f2b,
                     float* __restrict__ out) {
    __shared__ float h[8][128];
    int c = threadIdx.x;
    for (int bb = 0; bb < 8; bb++) {
        float s = f1b[c];
        #pragma unroll 4
        for (int j = 0; j < 128; j++) s += f1w[c * 128 + j] * g_gmax[bb * 128 + j];
        h[bb][c] = fmaxf(s, 0.f);
    }
    __syncthreads();
    if (c < 16) {
        int bb = c >> 1, o = c & 1;
        float s = f2b[o];
        #pragma unroll 4
        for (int j = 0; j < 128; j++) s += f2w[o * 128 + j] * h[bb][j];
        out[bb * 2 + o] = s;
    }
}

// ---------------- launch ----------------
extern "C" void kernel_launch(void* const* d_in, const int* in_sizes, int n_in,
                              void* d_out, int out_size) {
    const float* x   = (const float*)d_in[0];
    const float* w1  = (const float*)d_in[1];
    const float* b1  = (const float*)d_in[2];
    const float* w2  = (const float*)d_in[3];
    const float* b2  = (const float*)d_in[4];
    const float* f1w = (const float*)d_in[5];
    const float* f1b = (const float*)d_in[6];
    const float* f2w = (const float*)d_in[7];
    const float* f2b = (const float*)d_in[8];
    float* out = (float*)d_out;

    cudaFuncSetAttribute(k_gemm, cudaFuncAttributeMaxDynamicSharedMemorySize, kDynSmem);

    k_pack<<<4096, 256>>>(w1, w2);
    k_init<<<1, 1024>>>();
    k_gemm<<<kMblocks, 256, kDynSmem>>>(x, b1, b2);
    k_fc<<<1, 128>>>(f1w, f1b, f2w, f2b, out);
}

// round 4
// speedup vs baseline: 1.7249x; 1.7249x over previous
#include <cuda_runtime.h>
#include <cuda_fp16.h>
#include <cstdint>
#include <cfloat>

// ---------------- problem constants ----------------
constexpr int  kWindow = 512, kE = 8, kC = 128;
constexpr long kLseq   = 2000000;
constexpr int  kNwin   = 3906;                 // L / WINDOW
constexpr int  kMrows  = 8 * kNwin;            // 31248
constexpr int  kMtile  = 128;
constexpr int  kMblocks = (kMrows + kMtile - 1) / kMtile;  // 245
constexpr int  kK      = 4096;                 // WINDOW * E
constexpr int  kKc     = 32;                   // K per stage
constexpr int  kKIter  = kK / kKc;             // 128
constexpr int  kN      = 256;                  // conv1: n 0..127, conv2: n 128..255

// smem: A32 4x16KB | B16 4x16KB | A16 4x8KB
constexpr int  OFF_B16 = 65536;
constexpr int  OFF_A16 = 131072;
constexpr unsigned kDynSmem = 163840;

// ---------------- device scratch ----------------
static __device__ __align__(16) __half g_wh[(size_t)kN * kK];   // 2 MB
static __device__ float g_gmax[8 * kC];
static __device__ float g_h[8 * kC];

// ---------------- helpers ----------------
__device__ __forceinline__ uint32_t smem_u32(const void* p) {
    return (uint32_t)__cvta_generic_to_shared(p);
}
#define SW128(off) ((uint32_t)(off) ^ ((((uint32_t)(off)) >> 3) & 0x70u))
#define SW64O(off) ((uint32_t)(off) ^ ((((uint32_t)(off)) >> 3) & 0x30u))

__device__ __forceinline__ void cpa16(uint32_t dst, const void* src) {
    asm volatile("cp.async.cg.shared.global [%0], [%1], 16;"
        :: "r"(dst), "l"(__cvta_generic_to_global(src)) : "memory");
}
__device__ __forceinline__ void cpa_commit() { asm volatile("cp.async.commit_group;" ::: "memory"); }
__device__ __forceinline__ void cpa_wait2()  { asm volatile("cp.async.wait_group 2;" ::: "memory"); }

__device__ __forceinline__ void ldsm4(uint32_t& r0, uint32_t& r1, uint32_t& r2, uint32_t& r3,
                                      uint32_t addr) {
    asm volatile("ldmatrix.sync.aligned.m8n8.x4.shared.b16 {%0,%1,%2,%3}, [%4];"
        : "=r"(r0), "=r"(r1), "=r"(r2), "=r"(r3) : "r"(addr));
}
__device__ __forceinline__ void mma16816(float* c, const uint32_t* a, const uint32_t* b) {
    asm volatile("mma.sync.aligned.m16n8k16.row.col.f32.f16.f16.f32 "
        "{%0,%1,%2,%3}, {%4,%5,%6,%7}, {%8,%9}, {%0,%1,%2,%3};"
        : "+f"(c[0]), "+f"(c[1]), "+f"(c[2]), "+f"(c[3])
        : "r"(a[0]), "r"(a[1]), "r"(a[2]), "r"(a[3]), "r"(b[0]), "r"(b[1]));
}
__device__ __forceinline__ void atomMaxF(float* a, float v) {
    if (v >= 0.f) atomicMax((int*)a, __float_as_int(v));
    else          atomicMin((unsigned int*)a, __float_as_uint(v));
}

// ---------------- pack weights: W[n][k], n=0..127 conv1, 128..255 conv2; k = w*8+e
__global__ void k_pack(const float* __restrict__ w1, const float* __restrict__ w2) {
    int t = blockIdx.x * blockDim.x + threadIdx.x;   // 0 .. 1048575
    int n = t >> 12, k = t & 4095;
    int c = n & 127, s = n >> 7;
    int e = k & 7, w = k >> 3;
    float v = (s ? w2 : w1)[(c * kE + e) * kWindow + w];
    g_wh[(size_t)n * kK + k] = __float2half_rn(v);
}

__global__ void k_init() { g_gmax[threadIdx.x] = -FLT_MAX; }

// ---------------- main fused GEMM ----------------
__global__ void __launch_bounds__(512, 1)
k_gemm(const float* __restrict__ x, const float* __restrict__ cb1, const float* __restrict__ cb2) {
    extern __shared__ char dsm[];
    __shared__ float sb1[128], sb2[128];

    const int tid = threadIdx.x, lane = tid & 31, wid = tid >> 5;
    const int wn = wid & 3, wm = wid >> 2;          // warp grid 4(M) x 4(N)
    const int qn = lane & 3, qm = lane >> 2;

    if (tid < 128) { sb1[tid] = cb1[tid]; sb2[tid] = cb2[tid]; }

    const long m0 = (long)blockIdx.x * kMtile;

    // A-load row pointers: thread covers rows q*64 + (tid>>3), q=0,1
    const float* rowp[2];
    #pragma unroll
    for (int q = 0; q < 2; q++) {
        long gm = m0 + q * 64 + (tid >> 3);
        if (gm >= kMrows) gm = 0;                   // clamp; excluded in epilogue
        int b = (int)(gm / kNwin);
        int n = (int)(gm - (long)b * kNwin);
        rowp[q] = x + (size_t)b * ((size_t)kLseq * kE) + (size_t)n * kK;
    }
    const int segA = tid & 7;                       // 16B granule within 128B A row

    auto issue = [&](int kc) {
        const int s = kc & 3;
        const uint32_t a32 = smem_u32(dsm) + s * 16384;
        const uint32_t b16 = smem_u32(dsm) + OFF_B16 + s * 16384;
        #pragma unroll
        for (int q = 0; q < 2; q++) {               // A: 1024 granules, swizzled staging
            uint32_t g = (uint32_t)(q * 512 + tid);
            cpa16(a32 + SW128(g * 16), rowp[q] + kc * kKc + segA * 4);
        }
        #pragma unroll
        for (int q = 0; q < 2; q++) {               // B: 1024 granules, SW64
            uint32_t g = (uint32_t)(q * 512 + tid);
            cpa16(b16 + SW64O(g * 16),
                  g_wh + (size_t)(g >> 2) * kK + kc * kKc + (g & 3) * 8);
        }
    };

    issue(0); cpa_commit();
    issue(1); cpa_commit();
    issue(2); cpa_commit();

    float acc[2][8][4];
    #pragma unroll
    for (int t = 0; t < 2; t++)
        #pragma unroll
        for (int j = 0; j < 8; j++)
            #pragma unroll
            for (int e = 0; e < 4; e++) acc[t][j][e] = 0.f;

    // per-lane ldmatrix geometry
    const int gA = lane >> 3;
    const int rowAo = ((gA & 1) ? 8 : 0) + (lane & 7);
    const int colA  = (gA >> 1) ? 16 : 0;
    const int rowBo = ((gA >> 1) ? 8 : 0) + (lane & 7);
    const int colB  = (gA & 1) ? 16 : 0;
    const int cr = tid >> 2, cq = tid & 3;          // convert mapping

    #pragma unroll 1
    for (int kc = 0; kc < kKIter; kc++) {
        const int s = kc & 3;
        char* a32p = dsm + s * 16384;
        char* a16p = dsm + OFF_A16 + s * 8192;

        cpa_wait2();
        __syncthreads();

        // convert fp32 staging -> fp16 A tile (conflict-free via swizzles)
        {
            uint32_t o0 = (uint32_t)(cr * 128 + ((2 * cq)     ^ (cr & 7)) * 16);
            uint32_t o1 = (uint32_t)(cr * 128 + ((2 * cq + 1) ^ (cr & 7)) * 16);
            float4 fa = *(const float4*)(a32p + o0);
            float4 fb = *(const float4*)(a32p + o1);
            __half2 t0 = __floats2half2_rn(fa.x, fa.y), t1 = __floats2half2_rn(fa.z, fa.w);
            __half2 t2 = __floats2half2_rn(fb.x, fb.y), t3 = __floats2half2_rn(fb.z, fb.w);
            *(uint4*)(a16p + SW64O((uint32_t)(cr * 64 + cq * 16))) =
                make_uint4(*(uint32_t*)&t0, *(uint32_t*)&t1, *(uint32_t*)&t2, *(uint32_t*)&t3);
        }
        __syncthreads();

        if (kc + 3 < kKIter) issue(kc + 3);
        cpa_commit();

        // compute this stage: 2 k16 steps
        const uint32_t a16 = smem_u32(dsm) + OFF_A16 + s * 8192;
        const uint32_t b16 = smem_u32(dsm) + OFF_B16 + s * 16384;
        #pragma unroll
        for (int kk = 0; kk < 2; kk++) {
            uint32_t a[2][4];
            #pragma unroll
            for (int t = 0; t < 2; t++) {
                int row = wm * 32 + t * 16 + rowAo;
                uint32_t off = (uint32_t)(row * 64 + kk * 32 + colA);
                ldsm4(a[t][0], a[t][1], a[t][2], a[t][3], a16 + SW64O(off));
            }
            uint32_t bf[8][2];
            #pragma unroll
            for (int j2 = 0; j2 < 4; j2++) {
                int row = wn * 64 + j2 * 16 + rowBo;
                uint32_t off = (uint32_t)(row * 64 + kk * 32 + colB);
                uint32_t r0, r1, r2, r3;
                ldsm4(r0, r1, r2, r3, b16 + SW64O(off));
                bf[2 * j2][0] = r0;     bf[2 * j2][1] = r1;
                bf[2 * j2 + 1][0] = r2; bf[2 * j2 + 1][1] = r3;
            }
            #pragma unroll
            for (int t = 0; t < 2; t++)
                #pragma unroll
                for (int j = 0; j < 8; j++)
                    mma16816(acc[t][j], a[t], bf[j]);
        }
    }

    // ---------------- fused epilogue ----------------
    __syncthreads();                                  // compute done; reuse dsm
    float* gate = (float*)dsm;                        // [128][128] fp32 = 64 KB

    if (wn >= 2) {                                    // conv2: sigmoid gates
        #pragma unroll
        for (int t = 0; t < 2; t++)
            #pragma unroll
            for (int j = 0; j < 8; j++) {
                int cb = (wn - 2) * 64 + j * 8 + qn * 2;
                float b2e = sb2[cb], b2o = sb2[cb + 1];
                #pragma unroll
                for (int rb = 0; rb < 2; rb++) {
                    int row = wm * 32 + t * 16 + qm + rb * 8;
                    float ge = acc[t][j][rb * 2 + 0] + b2e;
                    float go = acc[t][j][rb * 2 + 1] + b2o;
                    gate[row * 128 + cb]     = 1.f / (1.f + __expf(-ge));
                    gate[row * 128 + cb + 1] = 1.f / (1.f + __expf(-go));
                }
            }
    }
    __syncthreads();

    if (wn < 2) {                                     // conv1: value * gate, max-pool
        long mlast = m0 + kMtile - 1;
        const bool uniform = (mlast < kMrows) && ((m0 / kNwin) == (mlast / kNwin));
        const int bb0 = (int)(m0 / kNwin);

        #pragma unroll
        for (int j = 0; j < 8; j++) {
            int cb = wn * 64 + j * 8 + qn * 2;
            float b1e = sb1[cb], b1o = sb1[cb + 1];
            if (uniform) {
                float vE = -FLT_MAX, vO = -FLT_MAX;
                #pragma unroll
                for (int t = 0; t < 2; t++)
                    #pragma unroll
                    for (int rb = 0; rb < 2; rb++) {
                        int row = wm * 32 + t * 16 + qm + rb * 8;
                        vE = fmaxf(vE, (acc[t][j][rb * 2 + 0] + b1e) * gate[row * 128 + cb]);
                        vO = fmaxf(vO, (acc[t][j][rb * 2 + 1] + b1o) * gate[row * 128 + cb + 1]);
                    }
                #pragma unroll
                for (int o = 4; o < 32; o <<= 1) {
                    vE = fmaxf(vE, __shfl_xor_sync(0xFFFFFFFFu, vE, o));
                    vO = fmaxf(vO, __shfl_xor_sync(0xFFFFFFFFu, vO, o));
                }
                if (qm == 0) {
                    atomMaxF(&g_gmax[bb0 * kC + cb],     vE);
                    atomMaxF(&g_gmax[bb0 * kC + cb + 1], vO);
                }
            } else {
                #pragma unroll
                for (int t = 0; t < 2; t++)
                    #pragma unroll
                    for (int rb = 0; rb < 2; rb++) {
                        long gm = m0 + wm * 32 + t * 16 + qm + rb * 8;
                        if (gm < kMrows) {
                            int row = wm * 32 + t * 16 + qm + rb * 8;
                            int bb = (int)(gm / kNwin);
                            atomMaxF(&g_gmax[bb * kC + cb],
                                     (acc[t][j][rb * 2 + 0] + b1e) * gate[row * 128 + cb]);
                            atomMaxF(&g_gmax[bb * kC + cb + 1],
                                     (acc[t][j][rb * 2 + 1] + b1o) * gate[row * 128 + cb + 1]);
                        }
                    }
            }
        }
    }
}

// ---------------- FC head ----------------
__global__ void k_fc1(const float* __restrict__ f1w, const float* __restrict__ f1b) {
    __shared__ float gm[128];
    int b = blockIdx.x, c = threadIdx.x;
    gm[c] = g_gmax[b * 128 + c];
    __syncthreads();
    float s = f1b[c];
    const float4* wr = (const float4*)(f1w + c * 128);
    #pragma unroll 8
    for (int j = 0; j < 32; j++) {
        float4 w4 = wr[j];
        s += w4.x * gm[4 * j] + w4.y * gm[4 * j + 1] + w4.z * gm[4 * j + 2] + w4.w * gm[4 * j + 3];
    }
    g_h[b * 128 + c] = fmaxf(s, 0.f);
}

__global__ void k_fc2(const float* __restrict__ f2w, const float* __restrict__ f2b,
                      float* __restrict__ out) {
    int w = threadIdx.x >> 5, lane = threadIdx.x & 31;   // 16 warps
    int b = w >> 1, o = w & 1;
    float4 w4 = ((const float4*)(f2w + o * 128))[lane];
    float4 h4 = ((const float4*)(g_h + b * 128))[lane];
    float s = w4.x * h4.x + w4.y * h4.y + w4.z * h4.z + w4.w * h4.w;
    #pragma unroll
    for (int off = 16; off > 0; off >>= 1)
        s += __shfl_xor_sync(0xFFFFFFFFu, s, off);
    if (lane == 0) out[b * 2 + o] = s + f2b[o];
}

// ---------------- launch ----------------
extern "C" void kernel_launch(void* const* d_in, const int* in_sizes, int n_in,
                              void* d_out, int out_size) {
    const float* x   = (const float*)d_in[0];
    const float* w1  = (const float*)d_in[1];
    const float* b1  = (const float*)d_in[2];
    const float* w2  = (const float*)d_in[3];
    const float* b2  = (const float*)d_in[4];
    const float* f1w = (const float*)d_in[5];
    const float* f1b = (const float*)d_in[6];
    const float* f2w = (const float*)d_in[7];
    const float* f2b = (const float*)d_in[8];
    float* out = (float*)d_out;

    cudaFuncSetAttribute(k_gemm, cudaFuncAttributeMaxDynamicSharedMemorySize, kDynSmem);

    k_pack<<<4096, 256>>>(w1, w2);
    k_init<<<1, 1024>>>();
    k_gemm<<<kMblocks, 512, kDynSmem>>>(x, b1, b2);
    k_fc1<<<8, 128>>>(f1w, f1b);
    k_fc2<<<1, 512>>>(f2w, f2b, out);
}